// round 2
// baseline (speedup 1.0000x reference)
#include <cuda_runtime.h>
#include <cuda_bf16.h>

// Problem constants (reference: B=2048, T=50, N=100, V=50000, D=512)
#define D_DIM 512
#define T_TGT 50
#define N_NOI 100
#define K_TOT (T_TGT + N_NOI)   // 150
#define MAX_B 4096

// Scratch (device allocation is forbidden)
__device__ float g_partials[MAX_B];
__device__ int   g_idx_stride;   // 1 = int32 indices, 2 = int64 (read low word)

__device__ __forceinline__ float log_sigmoid(float x) {
    // ls(x) = min(x,0) - log1p(exp(-|x|))  (numerically stable)
    return fminf(x, 0.0f) - log1pf(__expf(-fabsf(x)));
}

// Detect whether index arrays are int32 or int64.
// If int64 (little-endian), odd int32 words are high words == 0 for values < 2^31.
// Random indices in [0, 50000): probability all 8 odd words are zero when data
// is actually int32 is (1/50000)^8 ~ 0.
__global__ void nsl_detect_kernel(const int* __restrict__ t32)
{
    int all_zero = 1;
    #pragma unroll
    for (int i = 0; i < 8; i++)
        if (t32[2 * i + 1] != 0) all_zero = 0;
    g_idx_stride = all_zero ? 2 : 1;
}

__global__ void __launch_bounds__(256, 8)
nsl_main_kernel(const float* __restrict__ features,
                const int* __restrict__ targets,
                const int* __restrict__ noises,
                const float* __restrict__ W)
{
    const int b    = blockIdx.x;
    const int tid  = threadIdx.x;
    const int warp = tid >> 5;
    const int lane = tid & 31;
    const int str  = g_idx_stride;

    __shared__ float4 sfeat[D_DIM / 4];   // 2 KB
    __shared__ float  wsum[8];

    const float4* fsrc = reinterpret_cast<const float4*>(features + (size_t)b * D_DIM);
    for (int i = tid; i < D_DIM / 4; i += blockDim.x)
        sfeat[i] = fsrc[i];
    __syncthreads();

    const int* tg = targets + (size_t)b * T_TGT * str;
    const int* ns = noises  + (size_t)b * N_NOI * str;

    float local = 0.0f;   // meaningful on lane 0 only

    // Each warp handles indices k = warp, warp+8, ... < 150
    for (int k = warp; k < K_TOT; k += 8) {
        int idx;
        float sgn;
        if (k < T_TGT) { idx = tg[k * str];            sgn =  1.0f; }
        else           { idx = ns[(k - T_TGT) * str];  sgn = -1.0f; }

        const float4* wrow = reinterpret_cast<const float4*>(W + (size_t)idx * D_DIM);

        float acc = 0.0f;
        #pragma unroll
        for (int j = 0; j < 4; j++) {
            float4 wv = wrow[j * 32 + lane];
            float4 fv = sfeat[j * 32 + lane];
            acc += wv.x * fv.x + wv.y * fv.y + wv.z * fv.z + wv.w * fv.w;
        }
        #pragma unroll
        for (int o = 16; o > 0; o >>= 1)
            acc += __shfl_xor_sync(0xFFFFFFFFu, acc, o);

        if (lane == 0)
            local += log_sigmoid(sgn * acc);
    }

    if (lane == 0) wsum[warp] = local;
    __syncthreads();

    if (tid == 0) {
        float s = 0.0f;
        #pragma unroll
        for (int w = 0; w < 8; w++) s += wsum[w];
        g_partials[b] = s;
    }
}

__global__ void nsl_reduce_kernel(float* __restrict__ out, int nb)
{
    __shared__ float red[256];
    const int tid = threadIdx.x;
    float s = 0.0f;
    for (int i = tid; i < nb; i += 256)
        s += g_partials[i];
    red[tid] = s;
    __syncthreads();
    for (int stride = 128; stride > 0; stride >>= 1) {
        if (tid < stride) red[tid] += red[tid + stride];
        __syncthreads();
    }
    if (tid == 0)
        out[0] = -red[0] / (float)K_TOT;
}

extern "C" void kernel_launch(void* const* d_in, const int* in_sizes, int n_in,
                              void* d_out, int out_size)
{
    const float* features = (const float*)d_in[0];
    const int*   targets  = (const int*)d_in[1];
    const int*   noises   = (const int*)d_in[2];
    const float* W        = (const float*)d_in[3];

    const int B = in_sizes[0] / D_DIM;   // 2048

    nsl_detect_kernel<<<1, 1>>>(targets);
    nsl_main_kernel<<<B, 256>>>(features, targets, noises, W);
    nsl_reduce_kernel<<<1, 256>>>((float*)d_out, B);
}

// round 3
// speedup vs baseline: 1.0063x; 1.0063x over previous
#include <cuda_runtime.h>
#include <cuda_fp16.h>

// Problem constants (reference: B=2048, T=50, N=100, V=50000, D=512)
#define D_DIM 512
#define T_TGT 50
#define N_NOI 100
#define K_TOT 150
#define V_MAX 50000
#define MAX_B 4096

// Scratch (__device__ globals: allocation APIs are forbidden)
__device__ __half        g_Wh[(size_t)V_MAX * D_DIM];  // 51.2 MB fp16 copy of W
__device__ float         g_partials[MAX_B];
__device__ int           g_idx_stride;                 // 1 = int32 indices, 2 = int64 low word
__device__ unsigned int  g_count;                      // zero-init; reset by last block each call

__device__ __forceinline__ float log_sigmoid(float x) {
    return fminf(x, 0.0f) - log1pf(__expf(-fabsf(x)));
}

// Convert W (fp32) -> g_Wh (fp16). Also performs index-dtype detection once.
__global__ void __launch_bounds__(256)
nsl_convert_kernel(const float* __restrict__ W, const int* __restrict__ t32, int nElem)
{
    if (blockIdx.x == 0 && threadIdx.x == 0) {
        int all_zero = 1;
        #pragma unroll
        for (int i = 0; i < 8; i++)
            if (t32[2 * i + 1] != 0) all_zero = 0;
        g_idx_stride = all_zero ? 2 : 1;   // int64 little-endian => odd words are 0
    }

    const float4* W4  = reinterpret_cast<const float4*>(W);
    uint4*        out = reinterpret_cast<uint4*>(g_Wh);
    const int n8     = nElem >> 3;                    // 8 floats -> 8 halves (16B) per iter
    const int stride = gridDim.x * blockDim.x;

    for (int i = blockIdx.x * blockDim.x + threadIdx.x; i < n8; i += stride) {
        float4 a = W4[2 * i];
        float4 b = W4[2 * i + 1];
        __half2 h0 = __floats2half2_rn(a.x, a.y);
        __half2 h1 = __floats2half2_rn(a.z, a.w);
        __half2 h2 = __floats2half2_rn(b.x, b.y);
        __half2 h3 = __floats2half2_rn(b.z, b.w);
        uint4 o;
        o.x = *reinterpret_cast<unsigned int*>(&h0);
        o.y = *reinterpret_cast<unsigned int*>(&h1);
        o.z = *reinterpret_cast<unsigned int*>(&h2);
        o.w = *reinterpret_cast<unsigned int*>(&h3);
        out[i] = o;
    }
}

// 8 halves (one uint4) dotted with 8 fp32 features (two float4), fp32 accumulate.
__device__ __forceinline__ float dot8(uint4 w, float4 f0, float4 f1) {
    float2 a0 = __half22float2(*reinterpret_cast<__half2*>(&w.x));
    float2 a1 = __half22float2(*reinterpret_cast<__half2*>(&w.y));
    float2 a2 = __half22float2(*reinterpret_cast<__half2*>(&w.z));
    float2 a3 = __half22float2(*reinterpret_cast<__half2*>(&w.w));
    float acc;
    acc = a0.x * f0.x;
    acc = fmaf(a0.y, f0.y, acc);
    acc = fmaf(a1.x, f0.z, acc);
    acc = fmaf(a1.y, f0.w, acc);
    acc = fmaf(a2.x, f1.x, acc);
    acc = fmaf(a2.y, f1.y, acc);
    acc = fmaf(a3.x, f1.z, acc);
    acc = fmaf(a3.y, f1.w, acc);
    return acc;
}

__global__ void __launch_bounds__(256)
nsl_main_kernel(const float* __restrict__ features,
                const int* __restrict__ targets,
                const int* __restrict__ noises,
                float* __restrict__ out, int B)
{
    const int b    = blockIdx.x;
    const int tid  = threadIdx.x;
    const int warp = tid >> 5;
    const int lane = tid & 31;
    const int str  = g_idx_stride;

    __shared__ float wsum[8];
    __shared__ int   is_last;

    // Per-lane feature registers. Lane owns W-half chunks c0 = lane, c1 = 32+lane,
    // covering feature floats [8*c .. 8*c+8) — constant across all 150 rows.
    const float4* f4 = reinterpret_cast<const float4*>(features + (size_t)b * D_DIM);
    float4 fA0 = f4[2 * lane];
    float4 fA1 = f4[2 * lane + 1];
    float4 fB0 = f4[64 + 2 * lane];
    float4 fB1 = f4[65 + 2 * lane];

    const int* tg = targets + (size_t)b * T_TGT * str;
    const int* ns = noises  + (size_t)b * N_NOI * str;

    // Preload this warp's indices: lane r holds index for k = warp + 8*r.
    const int count = (K_TOT - warp + 7) >> 3;   // rows this warp handles (18 or 19)
    int myidx = 0;
    {
        int k = warp + lane * 8;
        if (k < K_TOT)
            myidx = (k < T_TGT) ? tg[k * str] : ns[(k - T_TGT) * str];
    }

    float local = 0.0f;   // lane 0 only

    for (int r = 0; r < count; r++) {
        int idx = __shfl_sync(0xFFFFFFFFu, myidx, r);
        int k   = warp + r * 8;
        float sgn = (k < T_TGT) ? 1.0f : -1.0f;

        const uint4* wrow = reinterpret_cast<const uint4*>(g_Wh + (size_t)idx * D_DIM);
        uint4 wa = wrow[lane];
        uint4 wb = wrow[32 + lane];

        float acc = dot8(wa, fA0, fA1) + dot8(wb, fB0, fB1);

        #pragma unroll
        for (int o = 16; o > 0; o >>= 1)
            acc += __shfl_xor_sync(0xFFFFFFFFu, acc, o);

        if (lane == 0)
            local += log_sigmoid(sgn * acc);
    }

    if (lane == 0) wsum[warp] = local;
    __syncthreads();

    if (tid == 0) {
        float s = 0.0f;
        #pragma unroll
        for (int w = 0; w < 8; w++) s += wsum[w];
        g_partials[b] = s;
        __threadfence();
        unsigned v = atomicAdd(&g_count, 1u);
        is_last = (v == (unsigned)(gridDim.x - 1)) ? 1 : 0;
    }
    __syncthreads();

    // Last finished block performs the deterministic final reduction.
    if (is_last) {
        __shared__ float red[256];
        __threadfence();
        float s = 0.0f;
        for (int i = tid; i < B; i += 256)
            s += g_partials[i];
        red[tid] = s;
        __syncthreads();
        #pragma unroll
        for (int stride = 128; stride > 0; stride >>= 1) {
            if (tid < stride) red[tid] += red[tid + stride];
            __syncthreads();
        }
        if (tid == 0) {
            out[0] = -red[0] / (float)K_TOT;
            g_count = 0;   // reset for next graph replay
        }
    }
}

extern "C" void kernel_launch(void* const* d_in, const int* in_sizes, int n_in,
                              void* d_out, int out_size)
{
    const float* features = (const float*)d_in[0];
    const int*   targets  = (const int*)d_in[1];
    const int*   noises   = (const int*)d_in[2];
    const float* W        = (const float*)d_in[3];

    const int B      = in_sizes[0] / D_DIM;       // 2048
    const int nElemW = in_sizes[3];               // 50000*512

    nsl_convert_kernel<<<2048, 256>>>(W, targets, nElemW);
    nsl_main_kernel<<<B, 256>>>(features, targets, noises, (float*)d_out, B);
}

// round 4
// speedup vs baseline: 1.4752x; 1.4660x over previous
#include <cuda_runtime.h>
#include <cuda_fp16.h>

// Problem constants (reference: B=2048, T=50, N=100, V=50000, D=512)
#define D_DIM 512
#define T_TGT 50
#define N_NOI 100
#define K_TOT 150
#define V_MAX 50000
#define MAX_B 4096

// Scratch (__device__ globals: allocation APIs are forbidden)
__device__ __half        g_Wh[(size_t)V_MAX * D_DIM];  // 51.2 MB fp16 copy of W
__device__ float         g_partials[MAX_B];
__device__ int           g_idx_stride;                 // 1 = int32 indices, 2 = int64 low word
__device__ unsigned int  g_count;                      // zero-init; reset by last block each call

__device__ __forceinline__ float log_sigmoid(float x) {
    return fminf(x, 0.0f) - log1pf(__expf(-fabsf(x)));
}

// Convert W (fp32) -> g_Wh (fp16). Streaming reads keep fp16 table L2-resident.
// Also performs index-dtype detection.
__global__ void __launch_bounds__(256)
nsl_convert_kernel(const float* __restrict__ W, const int* __restrict__ t32, int nElem)
{
    if (blockIdx.x == 0 && threadIdx.x == 0) {
        int all_zero = 1;
        #pragma unroll
        for (int i = 0; i < 8; i++)
            if (t32[2 * i + 1] != 0) all_zero = 0;
        g_idx_stride = all_zero ? 2 : 1;   // int64 little-endian => odd words are 0
    }

    const float4* W4  = reinterpret_cast<const float4*>(W);
    uint4*        out = reinterpret_cast<uint4*>(g_Wh);
    const int n8     = nElem >> 3;
    const int stride = gridDim.x * blockDim.x;

    for (int i = blockIdx.x * blockDim.x + threadIdx.x; i < n8; i += stride) {
        float4 a = __ldcs(&W4[2 * i]);
        float4 b = __ldcs(&W4[2 * i + 1]);
        __half2 h0 = __floats2half2_rn(a.x, a.y);
        __half2 h1 = __floats2half2_rn(a.z, a.w);
        __half2 h2 = __floats2half2_rn(b.x, b.y);
        __half2 h3 = __floats2half2_rn(b.z, b.w);
        uint4 o;
        o.x = *reinterpret_cast<unsigned int*>(&h0);
        o.y = *reinterpret_cast<unsigned int*>(&h1);
        o.z = *reinterpret_cast<unsigned int*>(&h2);
        o.w = *reinterpret_cast<unsigned int*>(&h3);
        out[i] = o;
    }
}

__device__ __forceinline__ __half2 u2h2(unsigned int u) {
    return *reinterpret_cast<__half2*>(&u);
}

// Accumulate 8 halves (uint4) * 8 half features into half2 acc (4 HFMA2).
__device__ __forceinline__ __half2 fma8(uint4 w, const __half2* f, __half2 acc) {
    acc = __hfma2(u2h2(w.x), f[0], acc);
    acc = __hfma2(u2h2(w.y), f[1], acc);
    acc = __hfma2(u2h2(w.z), f[2], acc);
    acc = __hfma2(u2h2(w.w), f[3], acc);
    return acc;
}

// Compute one row's per-lane partial dot in fp32.
__device__ __forceinline__ float row_dot(const __half2* fA, const __half2* fB,
                                         int idx, int lane) {
    const uint4* wrow = reinterpret_cast<const uint4*>(g_Wh + (size_t)idx * D_DIM);
    uint4 wa = wrow[lane];
    uint4 wb = wrow[32 + lane];
    __half2 acc = __float2half2_rn(0.0f);
    acc = fma8(wa, fA, acc);
    acc = fma8(wb, fB, acc);
    float2 af = __half22float2(acc);
    return af.x + af.y;
}

__global__ void __launch_bounds__(256)
nsl_main_kernel(const float* __restrict__ features,
                const int* __restrict__ targets,
                const int* __restrict__ noises,
                float* __restrict__ out, int B)
{
    const int b    = blockIdx.x;
    const int tid  = threadIdx.x;
    const int warp = tid >> 5;
    const int lane = tid & 31;
    const int str  = g_idx_stride;

    __shared__ float wsum[16];
    __shared__ int   is_last;

    // Features for this lane's chunks, converted to half2 registers.
    // Chunk A = halves [8*lane, 8*lane+8), chunk B = halves [8*(32+lane), ...).
    __half2 fA[4], fB[4];
    {
        const float4* f4 = reinterpret_cast<const float4*>(features + (size_t)b * D_DIM);
        float4 a0 = f4[2 * lane],      a1 = f4[2 * lane + 1];
        float4 b0 = f4[64 + 2 * lane], b1 = f4[65 + 2 * lane];
        fA[0] = __floats2half2_rn(a0.x, a0.y);
        fA[1] = __floats2half2_rn(a0.z, a0.w);
        fA[2] = __floats2half2_rn(a1.x, a1.y);
        fA[3] = __floats2half2_rn(a1.z, a1.w);
        fB[0] = __floats2half2_rn(b0.x, b0.y);
        fB[1] = __floats2half2_rn(b0.z, b0.w);
        fB[2] = __floats2half2_rn(b1.x, b1.y);
        fB[3] = __floats2half2_rn(b1.z, b1.w);
    }

    const int* tg = targets + (size_t)b * T_TGT * str;
    const int* ns = noises  + (size_t)b * N_NOI * str;

    // Lane r preloads the index for row k = warp + 8*r.
    const int count = (K_TOT - warp + 7) >> 3;   // 19 for warps 0-5, 18 for 6-7
    int myidx = 0;
    {
        int k = warp + lane * 8;
        if (k < K_TOT)
            myidx = (k < T_TGT) ? tg[k * str] : ns[(k - T_TGT) * str];
    }

    float local = 0.0f;   // meaningful on lanes 0 and 16 only

    const int npairs = count >> 1;
    for (int p = 0; p < npairs; p++) {
        int r0 = 2 * p, r1 = 2 * p + 1;
        int idx0 = __shfl_sync(0xFFFFFFFFu, myidx, r0);
        int idx1 = __shfl_sync(0xFFFFFFFFu, myidx, r1);
        int k0 = warp + r0 * 8, k1 = warp + r1 * 8;

        float acc0 = row_dot(fA, fB, idx0, lane);
        float acc1 = row_dot(fA, fB, idx1, lane);

        // Paired reduction: one xor-16 step each, then shared 4-step chain.
        acc0 += __shfl_xor_sync(0xFFFFFFFFu, acc0, 16);
        acc1 += __shfl_xor_sync(0xFFFFFFFFu, acc1, 16);
        float m = (lane < 16) ? acc0 : acc1;
        #pragma unroll
        for (int o = 8; o > 0; o >>= 1)
            m += __shfl_xor_sync(0xFFFFFFFFu, m, o);

        // lane 0 holds row0 total, lane 16 holds row1 total.
        if ((lane & 15) == 0) {
            int   k   = (lane == 0) ? k0 : k1;
            float sgn = (k < T_TGT) ? 1.0f : -1.0f;
            local += log_sigmoid(sgn * m);
        }
    }

    if (count & 1) {   // leftover row for odd count
        int r = count - 1;
        int idx = __shfl_sync(0xFFFFFFFFu, myidx, r);
        int k   = warp + r * 8;
        float acc = row_dot(fA, fB, idx, lane);
        #pragma unroll
        for (int o = 16; o > 0; o >>= 1)
            acc += __shfl_xor_sync(0xFFFFFFFFu, acc, o);
        if (lane == 0) {
            float sgn = (k < T_TGT) ? 1.0f : -1.0f;
            local += log_sigmoid(sgn * acc);
        }
    }

    if ((lane & 15) == 0)
        wsum[2 * warp + (lane >> 4)] = local;
    __syncthreads();

    if (tid == 0) {
        float s = 0.0f;
        #pragma unroll
        for (int w = 0; w < 16; w++) s += wsum[w];
        g_partials[b] = s;
        __threadfence();
        unsigned v = atomicAdd(&g_count, 1u);
        is_last = (v == (unsigned)(gridDim.x - 1)) ? 1 : 0;
    }
    __syncthreads();

    // Last finished block performs the deterministic final reduction.
    if (is_last) {
        __shared__ float red[256];
        __threadfence();
        float s = 0.0f;
        for (int i = tid; i < B; i += 256)
            s += g_partials[i];
        red[tid] = s;
        __syncthreads();
        #pragma unroll
        for (int stride = 128; stride > 0; stride >>= 1) {
            if (tid < stride) red[tid] += red[tid + stride];
            __syncthreads();
        }
        if (tid == 0) {
            out[0] = -red[0] / (float)K_TOT;
            g_count = 0;   // reset for next graph replay
        }
    }
}

extern "C" void kernel_launch(void* const* d_in, const int* in_sizes, int n_in,
                              void* d_out, int out_size)
{
    const float* features = (const float*)d_in[0];
    const int*   targets  = (const int*)d_in[1];
    const int*   noises   = (const int*)d_in[2];
    const float* W        = (const float*)d_in[3];

    const int B      = in_sizes[0] / D_DIM;       // 2048
    const int nElemW = in_sizes[3];               // 50000*512

    nsl_convert_kernel<<<2048, 256>>>(W, targets, nElemW);
    nsl_main_kernel<<<B, 256>>>(features, targets, noises, (float*)d_out, B);
}

// round 5
// speedup vs baseline: 1.5371x; 1.0419x over previous
#include <cuda_runtime.h>
#include <cuda_fp16.h>

// Problem constants (reference: B=2048, T=50, N=100, V=50000, D=512)
#define D_DIM 512
#define T_TGT 50
#define N_NOI 100
#define K_TOT 150
#define V_MAX 50000
#define MAX_B 4096

// Scratch (__device__ globals: allocation APIs are forbidden)
__device__ __half        g_Wh[(size_t)V_MAX * D_DIM];  // 51.2 MB fp16 copy of W
__device__ float         g_partials[MAX_B];
__device__ int           g_idx_stride;                 // 1 = int32 indices, 2 = int64 low word
__device__ unsigned int  g_count;                      // zero-init; reset by last block each call

__device__ __forceinline__ float log_sigmoid(float x) {
    // ls(x) = min(x,0) - log(1 + exp(-|x|)); fast MUFU-based log/exp.
    return fminf(x, 0.0f) - __logf(1.0f + __expf(-fabsf(x)));
}

// Convert W (fp32) -> g_Wh (fp16). Streaming reads; fp16 table stays L2-resident.
// Also performs index-dtype detection.
__global__ void __launch_bounds__(256)
nsl_convert_kernel(const float* __restrict__ W, const int* __restrict__ t32, int nElem)
{
    if (blockIdx.x == 0 && threadIdx.x == 0) {
        int all_zero = 1;
        #pragma unroll
        for (int i = 0; i < 8; i++)
            if (t32[2 * i + 1] != 0) all_zero = 0;
        g_idx_stride = all_zero ? 2 : 1;   // int64 little-endian => odd words are 0
    }

    const float4* W4  = reinterpret_cast<const float4*>(W);
    uint4*        out = reinterpret_cast<uint4*>(g_Wh);
    const int n8     = nElem >> 3;            // units of 8 floats -> one uint4 of halves
    const int stride = gridDim.x * blockDim.x;
    const int tid0   = blockIdx.x * blockDim.x + threadIdx.x;

    // 2 output uint4 per loop step: 4 independent float4 loads in flight.
    for (int i = tid0; i < n8; i += 2 * stride) {
        int j = i + stride;
        float4 a0 = __ldcs(&W4[2 * i]);
        float4 a1 = __ldcs(&W4[2 * i + 1]);
        float4 b0, b1;
        if (j < n8) { b0 = __ldcs(&W4[2 * j]); b1 = __ldcs(&W4[2 * j + 1]); }

        uint4 o;
        __half2 h;
        h = __floats2half2_rn(a0.x, a0.y); o.x = *reinterpret_cast<unsigned int*>(&h);
        h = __floats2half2_rn(a0.z, a0.w); o.y = *reinterpret_cast<unsigned int*>(&h);
        h = __floats2half2_rn(a1.x, a1.y); o.z = *reinterpret_cast<unsigned int*>(&h);
        h = __floats2half2_rn(a1.z, a1.w); o.w = *reinterpret_cast<unsigned int*>(&h);
        out[i] = o;

        if (j < n8) {
            h = __floats2half2_rn(b0.x, b0.y); o.x = *reinterpret_cast<unsigned int*>(&h);
            h = __floats2half2_rn(b0.z, b0.w); o.y = *reinterpret_cast<unsigned int*>(&h);
            h = __floats2half2_rn(b1.x, b1.y); o.z = *reinterpret_cast<unsigned int*>(&h);
            h = __floats2half2_rn(b1.z, b1.w); o.w = *reinterpret_cast<unsigned int*>(&h);
            out[j] = o;
        }
    }
}

__device__ __forceinline__ __half2 u2h2(unsigned int u) {
    return *reinterpret_cast<__half2*>(&u);
}

// Per-lane fp32 partial for one row given its two uint4 weight chunks.
__device__ __forceinline__ float dot_chunks(uint4 wa, uint4 wb, const __half2* fA, const __half2* fB) {
    __half2 acc = __float2half2_rn(0.0f);
    acc = __hfma2(u2h2(wa.x), fA[0], acc);
    acc = __hfma2(u2h2(wa.y), fA[1], acc);
    acc = __hfma2(u2h2(wa.z), fA[2], acc);
    acc = __hfma2(u2h2(wa.w), fA[3], acc);
    acc = __hfma2(u2h2(wb.x), fB[0], acc);
    acc = __hfma2(u2h2(wb.y), fB[1], acc);
    acc = __hfma2(u2h2(wb.z), fB[2], acc);
    acc = __hfma2(u2h2(wb.w), fB[3], acc);
    float2 af = __half22float2(acc);
    return af.x + af.y;
}

__global__ void __launch_bounds__(256)
nsl_main_kernel(const float* __restrict__ features,
                const int* __restrict__ targets,
                const int* __restrict__ noises,
                float* __restrict__ out, int B)
{
    const int b    = blockIdx.x;
    const int tid  = threadIdx.x;
    const int warp = tid >> 5;
    const int lane = tid & 31;
    const int str  = g_idx_stride;

    __shared__ float wsum[32];
    __shared__ int   is_last;

    // Features for this lane's chunks as half2 registers.
    __half2 fA[4], fB[4];
    {
        const float4* f4 = reinterpret_cast<const float4*>(features + (size_t)b * D_DIM);
        float4 a0 = f4[2 * lane],      a1 = f4[2 * lane + 1];
        float4 b0 = f4[64 + 2 * lane], b1 = f4[65 + 2 * lane];
        fA[0] = __floats2half2_rn(a0.x, a0.y);
        fA[1] = __floats2half2_rn(a0.z, a0.w);
        fA[2] = __floats2half2_rn(a1.x, a1.y);
        fA[3] = __floats2half2_rn(a1.z, a1.w);
        fB[0] = __floats2half2_rn(b0.x, b0.y);
        fB[1] = __floats2half2_rn(b0.z, b0.w);
        fB[2] = __floats2half2_rn(b1.x, b1.y);
        fB[3] = __floats2half2_rn(b1.z, b1.w);
    }

    const int* tg = targets + (size_t)b * T_TGT * str;
    const int* ns = noises  + (size_t)b * N_NOI * str;

    // Lane r preloads the index for row k = warp + 8*r.
    const int count = (K_TOT - warp + 7) >> 3;   // 19 (warps 0-5) or 18 (warps 6-7)
    int myidx = 0;
    {
        int k = warp + lane * 8;
        if (k < K_TOT)
            myidx = (k < T_TGT) ? tg[k * str] : ns[(k - T_TGT) * str];
    }

    float local = 0.0f;   // meaningful on lanes 0, 8, 16, 24

    // ---- Groups of 4 rows: 8 independent LDG.128 in flight per iteration ----
    const int ngroups = count >> 2;
    for (int p = 0; p < ngroups; p++) {
        int r = 4 * p;
        int i0 = __shfl_sync(0xFFFFFFFFu, myidx, r);
        int i1 = __shfl_sync(0xFFFFFFFFu, myidx, r + 1);
        int i2 = __shfl_sync(0xFFFFFFFFu, myidx, r + 2);
        int i3 = __shfl_sync(0xFFFFFFFFu, myidx, r + 3);

        const uint4* w0 = reinterpret_cast<const uint4*>(g_Wh + (size_t)i0 * D_DIM);
        const uint4* w1 = reinterpret_cast<const uint4*>(g_Wh + (size_t)i1 * D_DIM);
        const uint4* w2 = reinterpret_cast<const uint4*>(g_Wh + (size_t)i2 * D_DIM);
        const uint4* w3 = reinterpret_cast<const uint4*>(g_Wh + (size_t)i3 * D_DIM);

        uint4 a0 = __ldcg(&w0[lane]), b0c = __ldcg(&w0[32 + lane]);
        uint4 a1 = __ldcg(&w1[lane]), b1c = __ldcg(&w1[32 + lane]);
        uint4 a2 = __ldcg(&w2[lane]), b2c = __ldcg(&w2[32 + lane]);
        uint4 a3 = __ldcg(&w3[lane]), b3c = __ldcg(&w3[32 + lane]);

        float s0 = dot_chunks(a0, b0c, fA, fB);
        float s1 = dot_chunks(a1, b1c, fA, fB);
        float s2 = dot_chunks(a2, b2c, fA, fB);
        float s3 = dot_chunks(a3, b3c, fA, fB);

        // 4-way merged butterfly: 9 shuffles total.
        s0 += __shfl_xor_sync(0xFFFFFFFFu, s0, 16);
        s1 += __shfl_xor_sync(0xFFFFFFFFu, s1, 16);
        s2 += __shfl_xor_sync(0xFFFFFFFFu, s2, 16);
        s3 += __shfl_xor_sync(0xFFFFFFFFu, s3, 16);
        float m01 = (lane < 16) ? s0 : s1;
        float m23 = (lane < 16) ? s2 : s3;
        m01 += __shfl_xor_sync(0xFFFFFFFFu, m01, 8);
        m23 += __shfl_xor_sync(0xFFFFFFFFu, m23, 8);
        float m = (lane & 8) ? m23 : m01;
        m += __shfl_xor_sync(0xFFFFFFFFu, m, 4);
        m += __shfl_xor_sync(0xFFFFFFFFu, m, 2);
        m += __shfl_xor_sync(0xFFFFFFFFu, m, 1);

        // lanes 0,8,16,24 hold rows r0, r2, r1, r3 respectively.
        if ((lane & 7) == 0) {
            int sel = lane >> 3;                       // 0,1,2,3
            int roff = (sel == 1) ? 16 : (sel == 2) ? 8 : (sel == 3) ? 24 : 0;
            int k = warp + 32 * p + roff;
            float sgn = (k < T_TGT) ? 1.0f : -1.0f;
            local += log_sigmoid(sgn * m);
        }
    }

    // ---- Remainder rows (2 or 3) ----
    int r = ngroups * 4;
    if (r + 1 < count) {   // a pair
        int i0 = __shfl_sync(0xFFFFFFFFu, myidx, r);
        int i1 = __shfl_sync(0xFFFFFFFFu, myidx, r + 1);
        const uint4* w0 = reinterpret_cast<const uint4*>(g_Wh + (size_t)i0 * D_DIM);
        const uint4* w1 = reinterpret_cast<const uint4*>(g_Wh + (size_t)i1 * D_DIM);
        uint4 a0 = __ldcg(&w0[lane]), b0c = __ldcg(&w0[32 + lane]);
        uint4 a1 = __ldcg(&w1[lane]), b1c = __ldcg(&w1[32 + lane]);
        float s0 = dot_chunks(a0, b0c, fA, fB);
        float s1 = dot_chunks(a1, b1c, fA, fB);
        s0 += __shfl_xor_sync(0xFFFFFFFFu, s0, 16);
        s1 += __shfl_xor_sync(0xFFFFFFFFu, s1, 16);
        float m = (lane < 16) ? s0 : s1;
        #pragma unroll
        for (int o = 8; o > 0; o >>= 1)
            m += __shfl_xor_sync(0xFFFFFFFFu, m, o);
        if ((lane & 15) == 0) {
            int k = warp + ((lane == 0) ? r : (r + 1)) * 8;
            float sgn = (k < T_TGT) ? 1.0f : -1.0f;
            local += log_sigmoid(sgn * m);
        }
        r += 2;
    }
    if (r < count) {       // a single
        int i0 = __shfl_sync(0xFFFFFFFFu, myidx, r);
        const uint4* w0 = reinterpret_cast<const uint4*>(g_Wh + (size_t)i0 * D_DIM);
        uint4 a0 = __ldcg(&w0[lane]), b0c = __ldcg(&w0[32 + lane]);
        float s0 = dot_chunks(a0, b0c, fA, fB);
        #pragma unroll
        for (int o = 16; o > 0; o >>= 1)
            s0 += __shfl_xor_sync(0xFFFFFFFFu, s0, o);
        if (lane == 0) {
            int k = warp + r * 8;
            float sgn = (k < T_TGT) ? 1.0f : -1.0f;
            local += log_sigmoid(sgn * s0);
        }
    }

    if ((lane & 7) == 0)
        wsum[4 * warp + (lane >> 3)] = local;
    __syncthreads();

    if (tid == 0) {
        float s = 0.0f;
        #pragma unroll
        for (int w = 0; w < 32; w++) s += wsum[w];
        g_partials[b] = s;
        __threadfence();
        unsigned v = atomicAdd(&g_count, 1u);
        is_last = (v == (unsigned)(gridDim.x - 1)) ? 1 : 0;
    }
    __syncthreads();

    // Last finished block performs the deterministic final reduction.
    if (is_last) {
        __shared__ float red[256];
        __threadfence();
        float s = 0.0f;
        for (int i = tid; i < B; i += 256)
            s += g_partials[i];
        red[tid] = s;
        __syncthreads();
        #pragma unroll
        for (int stride = 128; stride > 0; stride >>= 1) {
            if (tid < stride) red[tid] += red[tid + stride];
            __syncthreads();
        }
        if (tid == 0) {
            out[0] = -red[0] / (float)K_TOT;
            g_count = 0;   // reset for next graph replay
        }
    }
}

extern "C" void kernel_launch(void* const* d_in, const int* in_sizes, int n_in,
                              void* d_out, int out_size)
{
    const float* features = (const float*)d_in[0];
    const int*   targets  = (const int*)d_in[1];
    const int*   noises   = (const int*)d_in[2];
    const float* W        = (const float*)d_in[3];

    const int B      = in_sizes[0] / D_DIM;       // 2048
    const int nElemW = in_sizes[3];               // 50000*512

    nsl_convert_kernel<<<2048, 256>>>(W, targets, nElemW);
    nsl_main_kernel<<<B, 256>>>(features, targets, noises, (float*)d_out, B);
}